// round 17
// baseline (speedup 1.0000x reference)
#include <cuda_runtime.h>
#include <cstdint>

// out[64,14336] = x[64,4096] @ dequant(W_int) + bias + x.sum(-1)*u
// tf32 mma.sync; split-K=4 (448 CTAs, 2 CTAs/SM); 2-stage cp.async ring;
// W raw int32 in smem -> I2F (exact in tf32); per-group scale fold on
// D-fragment columns; deterministic partials+reduce.
// R17: x QUAD-interleaved ([k,k+4,k+8,k+12] contiguous) -> one LDS.128 serves
// TWO ks iterations: A path 64 LDS.64 -> 32 LDS.128 per warp-chunk.

#define TOKS   64
#define INF    4096
#define OUTF   14336
#define KC     64
#define NTILE  128
#define NTILES (OUTF / NTILE)   // 112
#define SPLITK 4
#define KPER   (INF / SPLITK)   // 1024
#define NCHUNK (KPER / KC)      // 16
#define NCTA   (NTILES * SPLITK) // 448
#define STAGES 2

// smem strides (words): W stride % 32 == 8 -> 136 (LDS.32 frags conflict-free)
//                       x stride % 32 == 16 -> 80 (LDS.128 quad frags conflict-free)
#define WSTR 136
#define XSTR 80
#define W_STAGE_WORDS (KC * WSTR)            // 8704
#define X_STAGE_WORDS (TOKS * XSTR)          // 5120
#define STAGE_WORDS   (W_STAGE_WORDS + X_STAGE_WORDS)   // 13824
#define STAGE_BYTES   (STAGE_WORDS * 4)                 // 55296
#define W_STAGE_BYTES (W_STAGE_WORDS * 4)               // 34816
#define SMEM_BYTES    (STAGES * STAGE_BYTES)            // 110592

__device__ float g_xtf[TOKS * INF];            // tf32-rounded x, k-quad-interleaved
__device__ float g_xsum[TOKS];
__device__ float g_part[SPLITK * TOKS * OUTF]; // split-K partials (14.7MB)

static __device__ __forceinline__ uint32_t f2tf(float f) {
    uint32_t r;
    asm("cvt.rna.tf32.f32 %0, %1;" : "=r"(r) : "f"(f));
    return r;
}
static __device__ __forceinline__ uint32_t smem_u32(const void* p) {
    uint32_t a;
    asm("{ .reg .u64 t; cvta.to.shared.u64 t, %1; cvt.u32.u64 %0, t; }" : "=r"(a) : "l"(p));
    return a;
}
static __device__ __forceinline__ void cpasync16(uint32_t dst, const void* src) {
    asm volatile("cp.async.cg.shared.global [%0], [%1], 16;" :: "r"(dst), "l"(src));
}
static __device__ __forceinline__ void mma8(float* d, const uint32_t* a, const uint32_t* b) {
    asm volatile(
        "mma.sync.aligned.m16n8k8.row.col.f32.tf32.tf32.f32 "
        "{%0,%1,%2,%3}, {%4,%5,%6,%7}, {%8,%9}, {%0,%1,%2,%3};"
        : "+f"(d[0]), "+f"(d[1]), "+f"(d[2]), "+f"(d[3])
        : "r"(a[0]), "r"(a[1]), "r"(a[2]), "r"(a[3]), "r"(b[0]), "r"(b[1]));
}

// ---------- prep: x -> tf32, k-QUAD-interleave; per-token row sums ----------
// within each 16-block: original j (0..15) stored at (j&3)*4 + (j>>2)
// -> [k0,k4,k8,k12, k1,k5,k9,k13, k2,k6,k10,k14, k3,k7,k11,k15]
__global__ void __launch_bounds__(256) prep_kernel(const float* __restrict__ x) {
    const int row = blockIdx.x;
    const int t = threadIdx.x;
    const float* xr = x + row * INF;
    float s = 0.f;
    #pragma unroll
    for (int i = 0; i < INF / 256; ++i) {
        const int k = t + i * 256;
        const float v = xr[k];
        s += v;
        const int j = k & 15;
        const int pos = (k & ~15) + ((j & 3) * 4 + (j >> 2));
        g_xtf[row * INF + pos] = __uint_as_float(f2tf(v));
    }
    #pragma unroll
    for (int off = 16; off; off >>= 1) s += __shfl_xor_sync(0xffffffffu, s, off);
    __shared__ float red[8];
    if ((t & 31) == 0) red[t >> 5] = s;
    __syncthreads();
    if (t < 8) {
        float v = red[t];
        #pragma unroll
        for (int off = 4; off; off >>= 1) v += __shfl_xor_sync(0xffu, v, off);
        if (t == 0) g_xsum[row] = v;
    }
}

// ---------- main GEMM (one split-K work unit per CTA) ----------
__global__ void __launch_bounds__(256, 2)
qbits_kernel(const int* __restrict__ W, const float* __restrict__ scales)
{
    extern __shared__ uint32_t smem[];
    const uint32_t sbase = smem_u32(smem);
    const int tid  = threadIdx.x;
    const int lane = tid & 31;
    const int warp = tid >> 5;          // 0..7
    const int wn   = warp;              // N: 16 cols each (warp tile m64n16)
    const int q    = lane & 3;
    const int l4   = lane >> 2;
    const int tile  = blockIdx.x % NTILES;
    const int split = blockIdx.x / NTILES;
    const int obase = tile * NTILE;
    const int kbase = split * KPER;

    // copy geometry (256 threads)
    const int*   wsrc = W + obase + (lane << 2);
    const float* xsrc = g_xtf + (tid >> 2) * INF + ((tid & 3) << 4);
    const uint32_t wdst_off = (uint32_t)((warp * WSTR + (lane << 2)) * 4);
    const uint32_t xdst_off = (uint32_t)(W_STAGE_BYTES +
                              (((tid >> 2) * XSTR + ((tid & 3) << 4)) * 4));

    float acc[4][2][4];   // [mt][nt][frag] scaled accumulators
    float accg[4][2][4];  // per-group raw accumulators
    #pragma unroll
    for (int mt = 0; mt < 4; ++mt)
        #pragma unroll
        for (int nt = 0; nt < 2; ++nt)
            #pragma unroll
            for (int j = 0; j < 4; ++j) { acc[mt][nt][j] = 0.f; accg[mt][nt][j] = 0.f; }

    auto issue = [&](int c, int s) {
        const int k0 = kbase + c * KC;
        const uint32_t wb = sbase + (uint32_t)(s * STAGE_BYTES);
        #pragma unroll
        for (int p = 0; p < 8; ++p)
            cpasync16(wb + wdst_off + (uint32_t)(p * 8 * WSTR * 4),
                      wsrc + (k0 + warp + 8 * p) * OUTF);
        #pragma unroll
        for (int i = 0; i < 4; ++i)
            cpasync16(wb + xdst_off + (uint32_t)(i * 16), xsrc + k0 + i * 4);
        asm volatile("cp.async.commit_group;" ::: "memory");
    };

    issue(0, 0);

    float2 sc2[2];        // per-D-column scales (cols wn*16 + nt*8 + 2q + {0,1})
    int st = 0;
    for (int c = 0; c < NCHUNK; ++c) {
        asm volatile("cp.async.wait_group 0;" ::: "memory");
        __syncthreads();
        if (c + 1 < NCHUNK) issue(c + 1, st ^ 1);

        if ((c & 1) == 0) {   // group start: fetch D-column scales
            const int g = split * (KPER / 128) + (c >> 1);
            const float* srow = scales + g * OUTF + obase + wn * 16 + 2 * q;
            #pragma unroll
            for (int nt = 0; nt < 2; ++nt)
                sc2[nt] = __ldg((const float2*)(srow + nt * 8));
        }

        const uint32_t* ws  = smem + st * STAGE_WORDS;
        const float4*   xs4 = (const float4*)(ws + W_STAGE_WORDS);

        #pragma unroll
        for (int ksp = 0; ksp < 4; ++ksp) {     // ks-pair: covers ks=2ksp, 2ksp+1
            // ---- B fragments + I2F for both sub-ks ----
            uint32_t bb[2][2][2];               // [sub][nt][reg]
            #pragma unroll
            for (int sub = 0; sub < 2; ++sub) {
                const int kk = (ksp * 2 + sub) * 8 + q;
                #pragma unroll
                for (int nt = 0; nt < 2; ++nt) {
                    const int col = wn * 16 + nt * 8 + l4;
                    const int w0 = (int)ws[kk * WSTR + col];
                    const int w1 = (int)ws[(kk + 4) * WSTR + col];
                    bb[sub][nt][0] = __float_as_uint((float)w0);  // exact in tf32
                    bb[sub][nt][1] = __float_as_uint((float)w1);
                }
            }
            // ---- A quads (one LDS.128 pair per mt serves both sub-ks) ----
            #pragma unroll
            for (int mt = 0; mt < 4; ++mt) {
                const int r = mt * 16 + l4;
                const float4 vlo = xs4[r * (XSTR / 4) + ksp * 4 + q];
                const float4 vhi = xs4[(r + 8) * (XSTR / 4) + ksp * 4 + q];
                uint32_t ae[4], ao[4];
                ae[0] = __float_as_uint(vlo.x); ae[1] = __float_as_uint(vhi.x);
                ae[2] = __float_as_uint(vlo.y); ae[3] = __float_as_uint(vhi.y);
                ao[0] = __float_as_uint(vlo.z); ao[1] = __float_as_uint(vhi.z);
                ao[2] = __float_as_uint(vlo.w); ao[3] = __float_as_uint(vhi.w);
                #pragma unroll
                for (int nt = 0; nt < 2; ++nt) mma8(accg[mt][nt], ae, bb[0][nt]);
                #pragma unroll
                for (int nt = 0; nt < 2; ++nt) mma8(accg[mt][nt], ao, bb[1][nt]);
            }
        }

        if (c & 1) {          // group end: fold per-D-column scale, reset raw acc
            #pragma unroll
            for (int mt = 0; mt < 4; ++mt)
                #pragma unroll
                for (int nt = 0; nt < 2; ++nt) {
                    acc[mt][nt][0] = fmaf(sc2[nt].x, accg[mt][nt][0], acc[mt][nt][0]);
                    acc[mt][nt][1] = fmaf(sc2[nt].y, accg[mt][nt][1], acc[mt][nt][1]);
                    acc[mt][nt][2] = fmaf(sc2[nt].x, accg[mt][nt][2], acc[mt][nt][2]);
                    acc[mt][nt][3] = fmaf(sc2[nt].y, accg[mt][nt][3], acc[mt][nt][3]);
                    accg[mt][nt][0] = 0.f; accg[mt][nt][1] = 0.f;
                    accg[mt][nt][2] = 0.f; accg[mt][nt][3] = 0.f;
                }
        }
        st ^= 1;
    }

    // ---- epilogue: write partial tile (reduce kernel adds bias/u) ----
    float* part = g_part + split * (TOKS * OUTF);
    #pragma unroll
    for (int mt = 0; mt < 4; ++mt) {
        #pragma unroll
        for (int jr = 0; jr < 2; ++jr) {
            const int row = mt * 16 + l4 + jr * 8;
            #pragma unroll
            for (int nt = 0; nt < 2; ++nt) {
                const int col = obase + wn * 16 + nt * 8 + 2 * q;
                float2 o2;
                o2.x = acc[mt][nt][jr * 2 + 0];
                o2.y = acc[mt][nt][jr * 2 + 1];
                *(float2*)(part + row * OUTF + col) = o2;
            }
        }
    }
}

// ---------- reduce: out = sum(partials) + bias + xsum*u ----------
__global__ void __launch_bounds__(256)
reduce_kernel(const float* __restrict__ u, const float* __restrict__ bias,
              float* __restrict__ out)
{
    const int idx = blockIdx.x * 256 + threadIdx.x;       // over float4 units
    const int t   = idx / (OUTF / 4);
    const int c4  = (idx % (OUTF / 4)) * 4;
    const float xs = g_xsum[t];
    const int base = t * OUTF + c4;
    float4 s0 = *(const float4*)(g_part + 0 * TOKS * OUTF + base);
    float4 s1 = *(const float4*)(g_part + 1 * TOKS * OUTF + base);
    float4 s2 = *(const float4*)(g_part + 2 * TOKS * OUTF + base);
    float4 s3 = *(const float4*)(g_part + 3 * TOKS * OUTF + base);
    const float4 bv = *(const float4*)(bias + c4);
    const float4 uv = *(const float4*)(u + c4);
    float4 r;
    r.x = (s0.x + s1.x) + (s2.x + s3.x) + bv.x + xs * uv.x;
    r.y = (s0.y + s1.y) + (s2.y + s3.y) + bv.y + xs * uv.y;
    r.z = (s0.z + s1.z) + (s2.z + s3.z) + bv.z + xs * uv.z;
    r.w = (s0.w + s1.w) + (s2.w + s3.w) + bv.w + xs * uv.w;
    *(float4*)(out + base) = r;
}

extern "C" void kernel_launch(void* const* d_in, const int* in_sizes, int n_in,
                              void* d_out, int out_size) {
    const float* x  = (const float*)d_in[0];
    const int*   W  = (const int*)d_in[1];
    const float* sc = (const float*)d_in[2];
    const float* u  = (const float*)d_in[3];
    const float* b  = (const float*)d_in[4];
    float* out = (float*)d_out;

    cudaFuncSetAttribute(qbits_kernel, cudaFuncAttributeMaxDynamicSharedMemorySize,
                         SMEM_BYTES);
    prep_kernel<<<TOKS, 256>>>(x);
    qbits_kernel<<<NCTA, 256, SMEM_BYTES>>>(W, sc);
    reduce_kernel<<<(TOKS * OUTF / 4) / 256, 256>>>(u, b, out);
}